// round 10
// baseline (speedup 1.0000x reference)
#include <cuda_runtime.h>
#include <cuda_bf16.h>
#include <stdint.h>

#define NN   20000
#define RR   32
#define EMBD 16
#define HID  128
#define NE   600000
#define NSEG (NN*RR)

#define EPB1 1024
#define GRID1 672
#define GRID_T 5200           // >= sum ceil(cnt_r/128) + ceil(NN/128)

// ---------------- device scratch ----------------
__device__ int      g_is64;
__device__ unsigned g_cnt_seg[NSEG];
__device__ int      g_rel_cnt[RR];
__device__ int      g_rel_ptr[RR + 1];
__device__ int      g_rel_cur[RR];
__device__ int      g_dcnt[NN];
__device__ int      g_dptr[NN + 1];
__device__ int      g_dst_cur[NN];
__device__ int      g_srcA[NE];
__device__ int      g_dstA[NE];
__device__ int      g_relA[NE];
__device__ unsigned g_epack[NE];
__device__ float    g_einv[NE];
__device__ int      g_slot[NE];          // rel-sorted pos -> dst-sorted msg slot
__device__ float    g_msg[(NE + NN) * HID];   // dst-sorted messages + root rows
__device__ __nv_bfloat16 g_h1hi[NN * HID];
__device__ __nv_bfloat16 g_h1lo[NN * HID];
__device__ __nv_bfloat16 g_w2hi[(RR + 1) * HID * HID];  // [r][n][k] (r=32 -> root2)
__device__ __nv_bfloat16 g_w2lo[(RR + 1) * HID * HID];

__device__ __forceinline__ uint32_t smem_u32(const void* p) {
    uint32_t a;
    asm("{ .reg .u64 t; cvta.to.shared.u64 t, %1; cvt.u32.u64 %0, t; }" : "=r"(a) : "l"(p));
    return a;
}

// warp-level bf16 MMA (baseline PTX, sm_80+): D += A(16x16) * B(16x8)
__device__ __forceinline__ void mma_bf16(float* c, const uint32_t* a, uint32_t b0, uint32_t b1) {
    asm volatile("mma.sync.aligned.m16n8k16.row.col.f32.bf16.bf16.f32 "
                 "{%0,%1,%2,%3}, {%4,%5,%6,%7}, {%8,%9}, {%0,%1,%2,%3};"
                 : "+f"(c[0]), "+f"(c[1]), "+f"(c[2]), "+f"(c[3])
                 : "r"(a[0]), "r"(a[1]), "r"(a[2]), "r"(a[3]), "r"(b0), "r"(b1));
}
__device__ __forceinline__ void ldsm_x4(uint32_t* r, uint32_t addr) {
    asm volatile("ldmatrix.sync.aligned.m8n8.x4.shared.b16 {%0,%1,%2,%3}, [%4];"
                 : "=r"(r[0]), "=r"(r[1]), "=r"(r[2]), "=r"(r[3]) : "r"(addr));
}

// tiles are 128 rows x 256 bytes; swizzle XORs row low bits into 16B-chunk index
__device__ __forceinline__ void st_row16(char* tile, int row, int chunk, uint4 v) {
    int byte = row * 256 + chunk * 16;
    byte ^= (byte >> 4) & 0x70;
    *(uint4*)(tile + byte) = v;
}
__device__ __forceinline__ uint32_t frag_addr(uint32_t base, int row0, int kb, int lane) {
    int byte = (row0 + (lane & 15)) * 256 + kb + ((lane >> 4) << 4);
    byte ^= (byte >> 4) & 0x70;
    return base + (uint32_t)byte;
}

// ---------------- preprocessing ----------------
__global__ void k_sniff(const int* ei) {
    __shared__ int ok;
    if (threadIdx.x == 0) ok = 1;
    __syncthreads();
    int hi = ei[2 * threadIdx.x + 1];
    if (hi != 0) atomicExch(&ok, 0);
    __syncthreads();
    if (threadIdx.x == 0) g_is64 = ok;
}

__global__ void k_zero() {
    int i = blockIdx.x * blockDim.x + threadIdx.x;
    if (i < NSEG) g_cnt_seg[i] = 0u;
    if (i < RR)   g_rel_cnt[i] = 0;
    if (i < NN)   g_dcnt[i] = 0;
}

__global__ void k_decode(const void* ei, const void* et) {
    int e = blockIdx.x * blockDim.x + threadIdx.x;
    if (e >= NE) return;
    if (g_is64) {
        const long long* a = (const long long*)ei;
        const long long* b = (const long long*)et;
        g_srcA[e] = (int)a[e];
        g_dstA[e] = (int)a[NE + e];
        g_relA[e] = (int)b[e];
    } else {
        const int* a = (const int*)ei;
        const int* b = (const int*)et;
        g_srcA[e] = a[e];
        g_dstA[e] = a[NE + e];
        g_relA[e] = b[e];
    }
}

__global__ void k_count() {
    __shared__ int sh[RR];
    int t = threadIdx.x;
    if (t < RR) sh[t] = 0;
    __syncthreads();
    int e = blockIdx.x * blockDim.x + t;
    if (e < NE) {
        int r = g_relA[e], d = g_dstA[e];
        atomicAdd(&g_cnt_seg[d * RR + r], 1u);
        atomicAdd(&g_dcnt[d], 1);
        atomicAdd(&sh[r], 1);
    }
    __syncthreads();
    if (t < RR && sh[t]) atomicAdd(&g_rel_cnt[t], sh[t]);
}

__global__ void k_scan() {
    int acc = 0;
    for (int r = 0; r < RR; r++) {
        g_rel_ptr[r] = acc;
        g_rel_cur[r] = acc;
        acc += g_rel_cnt[r];
    }
    g_rel_ptr[RR] = acc;
}

// prefix scan of dst counts (single block)
__global__ void k_dscan() {
    __shared__ int part[256];
    const int t = threadIdx.x;
    const int CH = (NN + 255) / 256;
    int lo = t * CH, hi = min(lo + CH, NN);
    int s = 0;
    for (int i = lo; i < hi; i++) s += g_dcnt[i];
    part[t] = s;
    __syncthreads();
    for (int off = 1; off < 256; off <<= 1) {
        int v = (t >= off) ? part[t - off] : 0;
        __syncthreads();
        part[t] += v;
        __syncthreads();
    }
    int run = (t == 0) ? 0 : part[t - 1];
    for (int i = lo; i < hi; i++) {
        g_dptr[i] = run;
        g_dst_cur[i] = run;
        run += g_dcnt[i];
    }
    if (t == 255) g_dptr[NN] = NE;
}

__global__ void k_scatter() {
    int e = blockIdx.x * blockDim.x + threadIdx.x;
    if (e >= NE) return;
    int r = g_relA[e], s = g_srcA[e], d = g_dstA[e];
    int pos  = atomicAdd(&g_rel_cur[r], 1);
    int slot = atomicAdd(&g_dst_cur[d], 1);
    g_epack[pos] = (unsigned)s | ((unsigned)d << 16);
    g_einv[pos]  = 1.0f / (float)g_cnt_seg[d * RR + r];
    g_slot[pos]  = slot;
}

// transpose + split layer-2 weights: g_w2*[((r*128+n)*128)+k] = split(W[r][k][n])
__global__ void k_wcvt(const float* __restrict__ W2, const float* __restrict__ root2) {
    int idx = blockIdx.x * blockDim.x + threadIdx.x;
    if (idx >= (RR + 1) * HID * HID) return;
    int r = idx >> 14, n = (idx >> 7) & 127, k = idx & 127;
    float w = (r < RR) ? W2[((size_t)r * HID + k) * HID + n] : root2[(size_t)k * HID + n];
    __nv_bfloat16 hi = __float2bfloat16(w);
    __nv_bfloat16 lo = __float2bfloat16(w - __bfloat162float(hi));
    g_w2hi[idx] = hi;
    g_w2lo[idx] = lo;
}

// ---------------- layer 1: scalar weight-stationary, STG messages ----------------
template <int F, int EPB>
__global__ void __launch_bounds__(256)
k_layer(const float* __restrict__ X, const float* __restrict__ W,
        const float* __restrict__ Wroot) {
    extern __shared__ float sm[];
    float* Ws = sm;
    float* hb = sm + F * HID;

    const int tid  = threadIdx.x;
    const int lane = tid & 31;
    const int warp = tid >> 5;
    const int lane4 = lane * 4;

    int bid = blockIdx.x, acc = 0, rel = -1, chunk = 0, cnt = 0;
    #pragma unroll 1
    for (int r = 0; r <= RR; r++) {
        int c  = (r < RR) ? g_rel_cnt[r] : NN;
        int nb = (c + EPB - 1) / EPB;
        if (bid < acc + nb) { rel = r; chunk = bid - acc; cnt = c; break; }
        acc += nb;
    }
    if (rel < 0) return;

    const float* Wp = (rel < RR) ? (W + (size_t)rel * F * HID) : Wroot;
    const int base   = (rel < RR) ? g_rel_ptr[rel] : 0;
    const int cstart = chunk * EPB;

    for (int i = tid * 4; i < F * HID; i += 256 * 4)
        *(float4*)&Ws[i] = *(const float4*)&Wp[i];
    __syncthreads();

    float* hbw = hb + warp * (8 * F);
    const int ngroups = EPB / 8;

    for (int g = warp; g < ngroups; g += 8) {
        int gbase = cstart + g * 8;
        if (gbase >= cnt) break;

        int ms = 0, msl = 0; float mi = 0.0f;
        if (lane < 8) {
            int gl = gbase + lane;
            if (gl < cnt) {
                if (rel < RR) {
                    unsigned pk = g_epack[base + gl];
                    ms  = (int)(pk & 0xFFFFu);
                    mi  = g_einv[base + gl];
                    msl = g_slot[base + gl];
                } else {
                    ms = gl; mi = 1.0f; msl = NE + gl;   // root row
                }
            }
        }
        int srcs[8], slts[8]; float invs[8];
        #pragma unroll
        for (int e = 0; e < 8; e++) {
            srcs[e] = __shfl_sync(0xffffffffu, ms, e);
            slts[e] = __shfl_sync(0xffffffffu, msl, e);
            invs[e] = __shfl_sync(0xffffffffu, mi, e);
        }

        __syncwarp();
        if (lane < 16) {
            #pragma unroll
            for (int e = 0; e < 8; e++)
                hbw[e * F + lane] = X[(size_t)srcs[e] * F + lane];
        }
        __syncwarp();

        float a0[8], a1[8], a2[8], a3[8];
        #pragma unroll
        for (int e = 0; e < 8; e++) { a0[e] = a1[e] = a2[e] = a3[e] = 0.0f; }

        #pragma unroll 4
        for (int f = 0; f < F; f++) {
            float4 wv = *(float4*)&Ws[f * HID + lane4];
            #pragma unroll
            for (int e = 0; e < 8; e++) {
                float hv = hbw[e * F + f];
                a0[e] += hv * wv.x;
                a1[e] += hv * wv.y;
                a2[e] += hv * wv.z;
                a3[e] += hv * wv.w;
            }
        }

        #pragma unroll
        for (int e = 0; e < 8; e++) {
            float iv = invs[e];
            if (iv > 0.0f) {
                *(float4*)&g_msg[(size_t)slts[e] * HID + lane4] =
                    make_float4(a0[e] * iv, a1[e] * iv, a2[e] * iv, a3[e] * iv);
            }
        }
        __syncwarp();
    }
}

// ---------------- reduce: sum dst-sorted msgs (+root row) ----------------
// mode 0: +b1, relu, bf16-split -> g_h1hi/lo.   mode 1: +b2 -> out.
__global__ void __launch_bounds__(256)
k_reduce(const float* __restrict__ bias, float* __restrict__ out, int mode) {
    const int wid = threadIdx.x >> 5, lane = threadIdx.x & 31;
    int d = blockIdx.x * 8 + wid;
    if (d >= NN) return;
    const int l4 = lane * 4;

    float4 A = *(const float4*)&g_msg[(size_t)(NE + d) * HID + l4];  // root row
    float4 B = make_float4(0, 0, 0, 0), C = make_float4(0, 0, 0, 0), D = make_float4(0, 0, 0, 0);
    int s = g_dptr[d], e = g_dptr[d + 1];
    int i = s;
    for (; i + 4 <= e; i += 4) {
        float4 v0 = *(const float4*)&g_msg[(size_t)(i + 0) * HID + l4];
        float4 v1 = *(const float4*)&g_msg[(size_t)(i + 1) * HID + l4];
        float4 v2 = *(const float4*)&g_msg[(size_t)(i + 2) * HID + l4];
        float4 v3 = *(const float4*)&g_msg[(size_t)(i + 3) * HID + l4];
        A.x += v0.x; A.y += v0.y; A.z += v0.z; A.w += v0.w;
        B.x += v1.x; B.y += v1.y; B.z += v1.z; B.w += v1.w;
        C.x += v2.x; C.y += v2.y; C.z += v2.z; C.w += v2.w;
        D.x += v3.x; D.y += v3.y; D.z += v3.z; D.w += v3.w;
    }
    for (; i < e; i++) {
        float4 v = *(const float4*)&g_msg[(size_t)i * HID + l4];
        A.x += v.x; A.y += v.y; A.z += v.z; A.w += v.w;
    }
    float4 bb = *(const float4*)&bias[l4];
    float r0 = A.x + B.x + C.x + D.x + bb.x;
    float r1 = A.y + B.y + C.y + D.y + bb.y;
    float r2 = A.z + B.z + C.z + D.z + bb.z;
    float r3 = A.w + B.w + C.w + D.w + bb.w;

    if (mode == 0) {
        r0 = fmaxf(r0, 0.0f); r1 = fmaxf(r1, 0.0f);
        r2 = fmaxf(r2, 0.0f); r3 = fmaxf(r3, 0.0f);
        __nv_bfloat16 h0 = __float2bfloat16(r0), h1 = __float2bfloat16(r1);
        __nv_bfloat16 h2 = __float2bfloat16(r2), h3 = __float2bfloat16(r3);
        __nv_bfloat162 ph0, ph1, pl0, pl1;
        ph0.x = h0; ph0.y = h1; ph1.x = h2; ph1.y = h3;
        pl0.x = __float2bfloat16(r0 - __bfloat162float(h0));
        pl0.y = __float2bfloat16(r1 - __bfloat162float(h1));
        pl1.x = __float2bfloat16(r2 - __bfloat162float(h2));
        pl1.y = __float2bfloat16(r3 - __bfloat162float(h3));
        *(__nv_bfloat162*)&g_h1hi[(size_t)d * HID + l4]     = ph0;
        *(__nv_bfloat162*)&g_h1hi[(size_t)d * HID + l4 + 2] = ph1;
        *(__nv_bfloat162*)&g_h1lo[(size_t)d * HID + l4]     = pl0;
        *(__nv_bfloat162*)&g_h1lo[(size_t)d * HID + l4 + 2] = pl1;
    } else {
        *(float4*)&out[(size_t)d * HID + l4] = make_float4(r0, r1, r2, r3);
    }
}

// ---------------- layer 2: warp-MMA bf16-split GEMM per 128-edge tile ----------------
// SMEM: A_hi 32K | A_lo 32K | W_hi 32K | W_lo 32K | meta
#define S_AHI 0
#define S_ALO 32768
#define S_WHI 65536
#define S_WLO 98304
#define S_SRC 131072
#define S_SLOT 131584
#define S_INV 132096
#define S_SMEM 132608

__global__ void __launch_bounds__(256, 1)
k_tgemm() {
    extern __shared__ char smp[];
    const int tid  = threadIdx.x;
    const int wid  = tid >> 5;
    const int lane = tid & 31;

    // map block -> (rel 0..32, tile of 128)
    int bid = blockIdx.x, acc = 0, rel = -1, tile = 0, cnt = 0;
    #pragma unroll 1
    for (int r = 0; r <= RR; r++) {
        int c  = (r < RR) ? g_rel_cnt[r] : NN;
        int nb = (c + 127) >> 7;
        if (bid < acc + nb) { rel = r; tile = bid - acc; cnt = c; break; }
        acc += nb;
    }
    if (rel < 0) return;

    const int base  = (rel < RR) ? g_rel_ptr[rel] : 0;
    const int tbase = tile << 7;

    uint32_t sbase = smem_u32(smp);
    int*   s_src  = (int*)(smp + S_SRC);
    int*   s_slot = (int*)(smp + S_SLOT);
    float* s_inv  = (float*)(smp + S_INV);

    if (tid < 128) {
        int s = 0, sl = 0; float iv = 0.0f;
        int gl = tbase + tid;
        if (gl < cnt) {
            if (rel < RR) {
                unsigned pk = g_epack[base + gl];
                s  = (int)(pk & 0xFFFFu);
                iv = g_einv[base + gl];
                sl = g_slot[base + gl];
            } else {
                s = gl; iv = 1.0f; sl = NE + gl;
            }
        }
        s_src[tid] = s; s_slot[tid] = sl; s_inv[tid] = iv;
    }
    __syncthreads();

    // stage W (this relation) and gathered A rows, swizzled
    {
        int row = tid >> 1, half = tid & 1;
        const uint4* wh = (const uint4*)&g_w2hi[((size_t)rel * HID + row) * HID];
        const uint4* wl = (const uint4*)&g_w2lo[((size_t)rel * HID + row) * HID];
        int src = s_src[row];
        const uint4* rh = (const uint4*)&g_h1hi[(size_t)src * HID];
        const uint4* rl = (const uint4*)&g_h1lo[(size_t)src * HID];
        #pragma unroll
        for (int j = 0; j < 8; j++) {
            int ch = half * 8 + j;
            st_row16((char*)smp + S_WHI, row, ch, wh[ch]);
            st_row16((char*)smp + S_WLO, row, ch, wl[ch]);
            st_row16((char*)smp + S_AHI, row, ch, rh[ch]);
            st_row16((char*)smp + S_ALO, row, ch, rl[ch]);
        }
    }
    __syncthreads();

    // warp w: rows 16w..16w+15, full N=128
    float accm[16][4];
    #pragma unroll
    for (int nt = 0; nt < 16; nt++)
        #pragma unroll
        for (int i = 0; i < 4; i++) accm[nt][i] = 0.0f;

    uint32_t ah[4], al[4], bh[4], bl[4];
    #pragma unroll 1
    for (int kc = 0; kc < 8; kc++) {
        int kb = kc * 32;
        ldsm_x4(ah, frag_addr(sbase + S_AHI, wid * 16, kb, lane));
        ldsm_x4(al, frag_addr(sbase + S_ALO, wid * 16, kb, lane));
        #pragma unroll
        for (int ntp = 0; ntp < 8; ntp++) {
            ldsm_x4(bh, frag_addr(sbase + S_WHI, ntp * 16, kb, lane));
            ldsm_x4(bl, frag_addr(sbase + S_WLO, ntp * 16, kb, lane));
            mma_bf16(accm[2 * ntp],     ah, bh[0], bh[2]);
            mma_bf16(accm[2 * ntp],     ah, bl[0], bl[2]);
            mma_bf16(accm[2 * ntp],     al, bh[0], bh[2]);
            mma_bf16(accm[2 * ntp + 1], ah, bh[1], bh[3]);
            mma_bf16(accm[2 * ntp + 1], ah, bl[1], bl[3]);
            mma_bf16(accm[2 * ntp + 1], al, bh[1], bh[3]);
        }
    }

    // epilogue: scaled STG.64 to dst-sorted msg slots (no atomics)
    {
        int g = lane >> 2, t4 = lane & 3;
        int r0 = wid * 16 + g, r1 = r0 + 8;
        float iv0 = s_inv[r0], iv1 = s_inv[r1];
        float* m0 = g_msg + (size_t)s_slot[r0] * HID + t4 * 2;
        float* m1 = g_msg + (size_t)s_slot[r1] * HID + t4 * 2;
        #pragma unroll
        for (int nt = 0; nt < 16; nt++) {
            int off = nt * 8;
            if (iv0 > 0.0f)
                *(float2*)(m0 + off) = make_float2(accm[nt][0] * iv0, accm[nt][1] * iv0);
            if (iv1 > 0.0f)
                *(float2*)(m1 + off) = make_float2(accm[nt][2] * iv1, accm[nt][3] * iv1);
        }
    }
}

// ---------------- launch ----------------
extern "C" void kernel_launch(void* const* d_in, const int* in_sizes, int n_in,
                              void* d_out, int out_size) {
    const void*  ei = d_in[0];
    const void*  et = d_in[1];
    const float* x  = (const float*)d_in[2];
    const float* W1 = (const float*)d_in[3];
    const float* r1 = (const float*)d_in[4];
    const float* b1 = (const float*)d_in[5];
    const float* W2 = (const float*)d_in[6];
    const float* r2 = (const float*)d_in[7];
    const float* b2 = (const float*)d_in[8];
    float* out = (float*)d_out;

    const int SM1 = (EMBD * HID + 8 * 8 * EMBD) * 4;   // 12 KB

    static bool attr_done = false;
    if (!attr_done) {
        cudaFuncSetAttribute((const void*)k_tgemm,
                             cudaFuncAttributeMaxDynamicSharedMemorySize, S_SMEM);
        attr_done = true;
    }

    k_sniff  <<<1, 256>>>((const int*)ei);
    k_zero   <<<(NSEG + 255) / 256, 256>>>();
    k_decode <<<(NE + 255) / 256, 256>>>(ei, et);
    k_count  <<<(NE + 255) / 256, 256>>>();
    k_scan   <<<1, 1>>>();
    k_dscan  <<<1, 256>>>();
    k_scatter<<<(NE + 255) / 256, 256>>>();
    k_wcvt   <<<((RR + 1) * HID * HID + 255) / 256, 256>>>(W2, r2);

    // layer 1: scalar GEMM -> msg slots, then reduce (+b1, relu, split)
    k_layer<EMBD, EPB1><<<GRID1, 256, SM1>>>(x, W1, r1);
    k_reduce <<<(NN + 7) / 8, 256>>>(b1, nullptr, 0);
    // layer 2: warp-MMA GEMM -> msg slots, then reduce (+b2) -> out
    k_tgemm  <<<GRID_T, 256, S_SMEM>>>();
    k_reduce <<<(NN + 7) / 8, 256>>>(b2, out, 1);
}

// round 11
// speedup vs baseline: 1.6988x; 1.6988x over previous
#include <cuda_runtime.h>
#include <cuda_fp16.h>
#include <stdint.h>

#define NN   20000
#define RR   32
#define EMBD 16
#define HID  128
#define NE   600000
#define NSEG (NN*RR)

#define EPB1 1024
#define GRID1 672
#define TLOOP 8
#define GRID_T 768            // >= sum ceil(ceil(cnt_r/128)/TLOOP) + root groups

// ---------------- device scratch ----------------
__device__ int      g_is64;
__device__ unsigned g_cnt_seg[NSEG];
__device__ int      g_rel_cnt[RR];
__device__ int      g_rel_ptr[RR + 1];
__device__ int      g_rel_cur[RR];
__device__ int      g_srcA[NE];
__device__ int      g_dstA[NE];
__device__ int      g_relA[NE];
__device__ unsigned g_epack[NE];        // rel-sorted: src | dst<<16
__device__ float    g_einv[NE];         // rel-sorted: 1/count(dst,rel)
__device__ float    g_h1[NN * HID];     // fp32 hidden (layer-1 output, b1-init)
__device__ __half   g_h1f16[NN * HID];  // fp16 activations for MMA
__device__ __half   g_w2hi[(RR + 1) * HID * HID];  // [r][n][k] (r=32 -> root2)
__device__ __half   g_w2lo[(RR + 1) * HID * HID];

__device__ __forceinline__ void red_add_v4(float* p, float a, float b, float c, float d) {
    asm volatile("red.global.add.v4.f32 [%0], {%1,%2,%3,%4};"
                 :: "l"(p), "f"(a), "f"(b), "f"(c), "f"(d) : "memory");
}
__device__ __forceinline__ void red_add_v2(float* p, float a, float b) {
    asm volatile("red.global.add.v2.f32 [%0], {%1,%2};"
                 :: "l"(p), "f"(a), "f"(b) : "memory");
}
__device__ __forceinline__ uint32_t smem_u32(const void* p) {
    uint32_t a;
    asm("{ .reg .u64 t; cvta.to.shared.u64 t, %1; cvt.u32.u64 %0, t; }" : "=r"(a) : "l"(p));
    return a;
}

// warp-level fp16 MMA (baseline PTX, sm_80+): D += A(16x16) * B(16x8)
__device__ __forceinline__ void mma_f16(float* c, const uint32_t* a, uint32_t b0, uint32_t b1) {
    asm volatile("mma.sync.aligned.m16n8k16.row.col.f32.f16.f16.f32 "
                 "{%0,%1,%2,%3}, {%4,%5,%6,%7}, {%8,%9}, {%0,%1,%2,%3};"
                 : "+f"(c[0]), "+f"(c[1]), "+f"(c[2]), "+f"(c[3])
                 : "r"(a[0]), "r"(a[1]), "r"(a[2]), "r"(a[3]), "r"(b0), "r"(b1));
}
__device__ __forceinline__ void ldsm_x4(uint32_t* r, uint32_t addr) {
    asm volatile("ldmatrix.sync.aligned.m8n8.x4.shared.b16 {%0,%1,%2,%3}, [%4];"
                 : "=r"(r[0]), "=r"(r[1]), "=r"(r[2]), "=r"(r[3]) : "r"(addr));
}

// tiles: 128 rows x 256 bytes; swizzle XORs row low bits into 16B-chunk index
__device__ __forceinline__ void st_row16(char* tile, int row, int chunk, uint4 v) {
    int byte = row * 256 + chunk * 16;
    byte ^= (byte >> 4) & 0x70;
    *(uint4*)(tile + byte) = v;
}
__device__ __forceinline__ uint32_t frag_addr(uint32_t base, int row0, int kb, int lane) {
    int byte = (row0 + (lane & 15)) * 256 + kb + ((lane >> 4) << 4);
    byte ^= (byte >> 4) & 0x70;
    return base + (uint32_t)byte;
}

// ---------------- preprocessing ----------------
__global__ void k_sniff(const int* ei) {
    __shared__ int ok;
    if (threadIdx.x == 0) ok = 1;
    __syncthreads();
    int hi = ei[2 * threadIdx.x + 1];
    if (hi != 0) atomicExch(&ok, 0);
    __syncthreads();
    if (threadIdx.x == 0) g_is64 = ok;
}

__global__ void k_zero() {
    int i = blockIdx.x * blockDim.x + threadIdx.x;
    if (i < NSEG) g_cnt_seg[i] = 0u;
    if (i < RR)   g_rel_cnt[i] = 0;
}

__global__ void k_decode(const void* ei, const void* et) {
    int e = blockIdx.x * blockDim.x + threadIdx.x;
    if (e >= NE) return;
    if (g_is64) {
        const long long* a = (const long long*)ei;
        const long long* b = (const long long*)et;
        g_srcA[e] = (int)a[e];
        g_dstA[e] = (int)a[NE + e];
        g_relA[e] = (int)b[e];
    } else {
        const int* a = (const int*)ei;
        const int* b = (const int*)et;
        g_srcA[e] = a[e];
        g_dstA[e] = a[NE + e];
        g_relA[e] = b[e];
    }
}

__global__ void k_count() {
    __shared__ int sh[RR];
    int t = threadIdx.x;
    if (t < RR) sh[t] = 0;
    __syncthreads();
    int e = blockIdx.x * blockDim.x + t;
    if (e < NE) {
        int r = g_relA[e], d = g_dstA[e];
        atomicAdd(&g_cnt_seg[d * RR + r], 1u);
        atomicAdd(&sh[r], 1);
    }
    __syncthreads();
    if (t < RR && sh[t]) atomicAdd(&g_rel_cnt[t], sh[t]);
}

__global__ void k_scan() {
    int acc = 0;
    for (int r = 0; r < RR; r++) {
        g_rel_ptr[r] = acc;
        g_rel_cur[r] = acc;
        acc += g_rel_cnt[r];
    }
    g_rel_ptr[RR] = acc;
}

__global__ void k_scatter() {
    int e = blockIdx.x * blockDim.x + threadIdx.x;
    if (e >= NE) return;
    int r = g_relA[e], s = g_srcA[e], d = g_dstA[e];
    int pos = atomicAdd(&g_rel_cur[r], 1);
    g_epack[pos] = (unsigned)s | ((unsigned)d << 16);
    g_einv[pos]  = 1.0f / (float)g_cnt_seg[d * RR + r];
}

__global__ void k_init(const float* __restrict__ b1, const float* __restrict__ b2,
                       float* __restrict__ out) {
    int i = blockIdx.x * blockDim.x + threadIdx.x;
    if (i >= NN * HID) return;
    int h = i & (HID - 1);
    g_h1[i] = b1[h];
    out[i]  = b2[h];
}

// relu + fp16 convert of h1
__global__ void k_relu_cvt() {
    int i = blockIdx.x * blockDim.x + threadIdx.x;
    if (i >= NN * HID) return;
    g_h1f16[i] = __float2half(fmaxf(g_h1[i], 0.0f));
}

// transpose + fp16-split layer-2 weights: g_w2*[((r*128+n)*128)+k] = split(W[r][k][n])
__global__ void k_wcvt(const float* __restrict__ W2, const float* __restrict__ root2) {
    int idx = blockIdx.x * blockDim.x + threadIdx.x;
    if (idx >= (RR + 1) * HID * HID) return;
    int r = idx >> 14, n = (idx >> 7) & 127, k = idx & 127;
    float w = (r < RR) ? W2[((size_t)r * HID + k) * HID + n] : root2[(size_t)k * HID + n];
    __half hi = __float2half(w);
    __half lo = __float2half(w - __half2float(hi));
    g_w2hi[idx] = hi;
    g_w2lo[idx] = lo;
}

// ---------------- layer 1: scalar weight-stationary, RED into g_h1 ----------------
template <int F, int EPB>
__global__ void __launch_bounds__(256)
k_layer(const float* __restrict__ X, const float* __restrict__ W,
        const float* __restrict__ Wroot) {
    extern __shared__ float sm[];
    float* Ws = sm;
    float* hb = sm + F * HID;

    const int tid  = threadIdx.x;
    const int lane = tid & 31;
    const int warp = tid >> 5;
    const int lane4 = lane * 4;

    int bid = blockIdx.x, acc = 0, rel = -1, chunk = 0, cnt = 0;
    #pragma unroll 1
    for (int r = 0; r <= RR; r++) {
        int c  = (r < RR) ? g_rel_cnt[r] : NN;
        int nb = (c + EPB - 1) / EPB;
        if (bid < acc + nb) { rel = r; chunk = bid - acc; cnt = c; break; }
        acc += nb;
    }
    if (rel < 0) return;

    const float* Wp = (rel < RR) ? (W + (size_t)rel * F * HID) : Wroot;
    const int base   = (rel < RR) ? g_rel_ptr[rel] : 0;
    const int cstart = chunk * EPB;

    for (int i = tid * 4; i < F * HID; i += 256 * 4)
        *(float4*)&Ws[i] = *(const float4*)&Wp[i];
    __syncthreads();

    float* hbw = hb + warp * (8 * F);
    const int ngroups = EPB / 8;

    for (int g = warp; g < ngroups; g += 8) {
        int gbase = cstart + g * 8;
        if (gbase >= cnt) break;

        int ms = 0, md = 0; float mi = 0.0f;
        if (lane < 8) {
            int gl = gbase + lane;
            if (gl < cnt) {
                if (rel < RR) {
                    unsigned pk = g_epack[base + gl];
                    ms = (int)(pk & 0xFFFFu);
                    md = (int)(pk >> 16);
                    mi = g_einv[base + gl];
                } else {
                    ms = gl; md = gl; mi = 1.0f;
                }
            }
        }
        int srcs[8], dsts[8]; float invs[8];
        #pragma unroll
        for (int e = 0; e < 8; e++) {
            srcs[e] = __shfl_sync(0xffffffffu, ms, e);
            dsts[e] = __shfl_sync(0xffffffffu, md, e);
            invs[e] = __shfl_sync(0xffffffffu, mi, e);
        }

        __syncwarp();
        if (lane < 16) {
            #pragma unroll
            for (int e = 0; e < 8; e++)
                hbw[e * F + lane] = X[(size_t)srcs[e] * F + lane];
        }
        __syncwarp();

        float a0[8], a1[8], a2[8], a3[8];
        #pragma unroll
        for (int e = 0; e < 8; e++) { a0[e] = a1[e] = a2[e] = a3[e] = 0.0f; }

        #pragma unroll 4
        for (int f = 0; f < F; f++) {
            float4 wv = *(float4*)&Ws[f * HID + lane4];
            #pragma unroll
            for (int e = 0; e < 8; e++) {
                float hv = hbw[e * F + f];
                a0[e] += hv * wv.x;
                a1[e] += hv * wv.y;
                a2[e] += hv * wv.z;
                a3[e] += hv * wv.w;
            }
        }

        #pragma unroll
        for (int e = 0; e < 8; e++) {
            float iv = invs[e];
            if (iv > 0.0f) {
                red_add_v4(g_h1 + (size_t)dsts[e] * HID + lane4,
                           a0[e] * iv, a1[e] * iv, a2[e] * iv, a3[e] * iv);
            }
        }
        __syncwarp();
    }
}

// ---------------- layer 2: warp-MMA fp16 GEMM, W-resident, TLOOP tiles/CTA ----------------
// SMEM: W_hi 32K | W_lo 32K | A 32K   (96 KB -> 2 CTAs/SM)
#define S_WHI 0
#define S_WLO 32768
#define S_A   65536
#define S_SMEM 98304

__global__ void __launch_bounds__(256)
k_tgemm(float* __restrict__ out) {
    extern __shared__ char smp[];
    const int tid  = threadIdx.x;
    const int wid  = tid >> 5;
    const int lane = tid & 31;
    uint32_t sbase = smem_u32(smp);

    // map block -> (rel 0..32, group of TLOOP tiles)
    int bid = blockIdx.x, acc = 0, rel = -1, grp = 0, cnt = 0;
    #pragma unroll 1
    for (int r = 0; r <= RR; r++) {
        int c  = (r < RR) ? g_rel_cnt[r] : NN;
        int nt = (c + 127) >> 7;
        int ng = (nt + TLOOP - 1) / TLOOP;
        if (bid < acc + ng) { rel = r; grp = bid - acc; cnt = c; break; }
        acc += ng;
    }
    if (rel < 0) return;

    const int base   = (rel < RR) ? g_rel_ptr[rel] : 0;
    const int ntile  = (cnt + 127) >> 7;
    const int tstart = grp * TLOOP;
    const int tend   = min(tstart + TLOOP, ntile);

    // stage W (hi/lo) once per CTA
    {
        int row = tid >> 1, half = tid & 1;
        const uint4* wh = (const uint4*)&g_w2hi[((size_t)rel * HID + row) * HID];
        const uint4* wl = (const uint4*)&g_w2lo[((size_t)rel * HID + row) * HID];
        #pragma unroll
        for (int j = 0; j < 8; j++) {
            int ch = half * 8 + j;
            st_row16(smp + S_WHI, row, ch, wh[ch]);
            st_row16(smp + S_WLO, row, ch, wl[ch]);
        }
    }

    for (int t = tstart; t < tend; t++) {
        const int tbase = t << 7;
        __syncthreads();   // W ready (first iter) / previous MMA+epilogue done

        // gather A rows (fp16) into swizzled tile
        {
            int row = tid >> 1, half = tid & 1;
            int gl = tbase + row;
            int src = 0;
            if (gl < cnt) src = (rel < RR) ? (int)(g_epack[base + gl] & 0xFFFFu) : gl;
            const uint4* rh = (const uint4*)&g_h1f16[(size_t)src * HID];
            #pragma unroll
            for (int j = 0; j < 8; j++) {
                int ch = half * 8 + j;
                st_row16(smp + S_A, row, ch, rh[ch]);
            }
        }
        __syncthreads();

        // warp w: rows 16w..16w+15, full N=128
        float accm[16][4];
        #pragma unroll
        for (int nt = 0; nt < 16; nt++)
            #pragma unroll
            for (int i = 0; i < 4; i++) accm[nt][i] = 0.0f;

        uint32_t a[4], bh[4], bl[4];
        #pragma unroll 1
        for (int kc = 0; kc < 8; kc++) {
            int kb = kc * 32;
            ldsm_x4(a, frag_addr(sbase + S_A, wid * 16, kb, lane));
            #pragma unroll
            for (int ntp = 0; ntp < 8; ntp++) {
                ldsm_x4(bh, frag_addr(sbase + S_WHI, ntp * 16, kb, lane));
                ldsm_x4(bl, frag_addr(sbase + S_WLO, ntp * 16, kb, lane));
                mma_f16(accm[2 * ntp],     a, bh[0], bh[2]);
                mma_f16(accm[2 * ntp],     a, bl[0], bl[2]);
                mma_f16(accm[2 * ntp + 1], a, bh[1], bh[3]);
                mma_f16(accm[2 * ntp + 1], a, bl[1], bl[3]);
            }
        }

        // epilogue: meta direct from gmem; scaled RED.v2 into out
        {
            int g = lane >> 2, t4 = lane & 3;
            int r0 = wid * 16 + g, r1 = r0 + 8;
            int gl0 = tbase + r0, gl1 = tbase + r1;
            int d0 = 0, d1 = 0; float iv0 = 0.0f, iv1 = 0.0f;
            if (gl0 < cnt) {
                if (rel < RR) { unsigned pk = g_epack[base + gl0]; d0 = (int)(pk >> 16); iv0 = g_einv[base + gl0]; }
                else          { d0 = gl0; iv0 = 1.0f; }
            }
            if (gl1 < cnt) {
                if (rel < RR) { unsigned pk = g_epack[base + gl1]; d1 = (int)(pk >> 16); iv1 = g_einv[base + gl1]; }
                else          { d1 = gl1; iv1 = 1.0f; }
            }
            float* o0 = out + (size_t)d0 * HID + t4 * 2;
            float* o1 = out + (size_t)d1 * HID + t4 * 2;
            #pragma unroll
            for (int nt = 0; nt < 16; nt++) {
                int off = nt * 8;
                if (iv0 > 0.0f) red_add_v2(o0 + off, accm[nt][0] * iv0, accm[nt][1] * iv0);
                if (iv1 > 0.0f) red_add_v2(o1 + off, accm[nt][2] * iv1, accm[nt][3] * iv1);
            }
        }
    }
}

// ---------------- launch ----------------
extern "C" void kernel_launch(void* const* d_in, const int* in_sizes, int n_in,
                              void* d_out, int out_size) {
    const void*  ei = d_in[0];
    const void*  et = d_in[1];
    const float* x  = (const float*)d_in[2];
    const float* W1 = (const float*)d_in[3];
    const float* r1 = (const float*)d_in[4];
    const float* b1 = (const float*)d_in[5];
    const float* W2 = (const float*)d_in[6];
    const float* r2 = (const float*)d_in[7];
    const float* b2 = (const float*)d_in[8];
    float* out = (float*)d_out;

    const int SM1 = (EMBD * HID + 8 * 8 * EMBD) * 4;   // 12 KB

    static bool attr_done = false;
    if (!attr_done) {
        cudaFuncSetAttribute((const void*)k_tgemm,
                             cudaFuncAttributeMaxDynamicSharedMemorySize, S_SMEM);
        attr_done = true;
    }

    k_sniff  <<<1, 256>>>((const int*)ei);
    k_zero   <<<(NSEG + 255) / 256, 256>>>();
    k_decode <<<(NE + 255) / 256, 256>>>(ei, et);
    k_count  <<<(NE + 255) / 256, 256>>>();
    k_scan   <<<1, 1>>>();
    k_scatter<<<(NE + 255) / 256, 256>>>();
    k_init   <<<(NN * HID + 255) / 256, 256>>>(b1, b2, out);
    k_wcvt   <<<((RR + 1) * HID * HID + 255) / 256, 256>>>(W2, r2);

    // layer 1: scalar GEMM, RED into g_h1 (b1-initialized)
    k_layer<EMBD, EPB1><<<GRID1, 256, SM1>>>(x, W1, r1);
    k_relu_cvt<<<(NN * HID + 255) / 256, 256>>>();
    // layer 2: fp16 warp-MMA, W-resident, RED into out (b2-initialized)
    k_tgemm  <<<GRID_T, 256, S_SMEM>>>(out);
}